// round 3
// baseline (speedup 1.0000x reference)
#include <cuda_runtime.h>

#define N_B 64
#define HW_ 1024
#define D_  512
#define K_  64
#define ROWS (N_B*HW_)
#define EPSF 1e-12f

// Scratch (allocation-free rule: __device__ globals)
__device__ float g_a[(size_t)ROWS * K_];      // softmax assignments [rows, K]
__device__ float g_asum[N_B * K_];            // sum over hw of a     [N, K]
__device__ float g_colsq[N_B * K_];           // per-(n,k) sum of v^2 [N, K]

// ---------------------------------------------------------------------------
// K0: zero accumulators (must re-zero every graph replay)
// ---------------------------------------------------------------------------
__global__ void zero_kernel() {
    int t = blockIdx.x * blockDim.x + threadIdx.x;
    if (t < N_B * K_) { g_asum[t] = 0.f; g_colsq[t] = 0.f; }
}

// ---------------------------------------------------------------------------
// K1: assignment GEMM (65536 x 64 x 512) + softmax + a_sum
// Block: 256 threads (16x16), tile BM=128 rows, BN=64 cols, BK=32.
// Thread micro-tile: 8 rows x 4 cols. Row's 64 cols live across 16 lanes
// (tx = tid & 15) -> softmax reductions via xor-shuffle within 16-lane group.
// ---------------------------------------------------------------------------
__launch_bounds__(256, 4)
__global__ void assign_kernel(const float* __restrict__ x,
                              const float* __restrict__ Wc,
                              const float* __restrict__ bc) {
    __shared__ float As[32][132];   // [d_k][row], 132 pad: rows 16B-aligned (528B)
    __shared__ float Bs[32][64];    // [d_k][col]
    __shared__ float red[16][64];

    const int tid = threadIdx.x;
    const int tx = tid & 15;        // col group
    const int ty = tid >> 4;        // row group
    const int row0 = blockIdx.x * 128;
    const int n = row0 >> 10;       // 1024 rows per n, blocks aligned

    float acc[8][4];
#pragma unroll
    for (int i = 0; i < 8; i++)
#pragma unroll
        for (int j = 0; j < 4; j++) acc[i][j] = 0.f;

    for (int kt = 0; kt < D_; kt += 32) {
        // x tile: 128 rows x 32 d, stored transposed As[d][row]
        {
            int r = tid >> 3;            // 0..31
            int c = (tid & 7) * 4;       // 0..28
#pragma unroll
            for (int p = 0; p < 4; p++) {
                int rr = r + p * 32;
                float4 v = *(const float4*)(x + (size_t)(row0 + rr) * D_ + kt + c);
                As[c + 0][rr] = v.x; As[c + 1][rr] = v.y;
                As[c + 2][rr] = v.z; As[c + 3][rr] = v.w;
            }
        }
        // W tile: 32 d x 64 k, direct copy
        {
            int r = tid >> 4;            // 0..15
            int c = (tid & 15) * 4;
#pragma unroll
            for (int p = 0; p < 2; p++) {
                int rr = r + p * 16;
                *(float4*)&Bs[rr][c] = *(const float4*)(Wc + (size_t)(kt + rr) * K_ + c);
            }
        }
        __syncthreads();
#pragma unroll
        for (int kk = 0; kk < 32; kk++) {
            float af[8], bf[4];
            *(float4*)&af[0] = *(const float4*)&As[kk][ty * 8];
            *(float4*)&af[4] = *(const float4*)&As[kk][ty * 8 + 4];
            *(float4*)&bf[0] = *(const float4*)&Bs[kk][tx * 4];
#pragma unroll
            for (int i = 0; i < 8; i++)
#pragma unroll
                for (int j = 0; j < 4; j++)
                    acc[i][j] = fmaf(af[i], bf[j], acc[i][j]);
        }
        __syncthreads();
    }

    // epilogue: + bias, softmax over 64 cols (16 lanes x 4 cols), store a
    float bfr[4];
    *(float4*)bfr = *(const float4*)(bc + tx * 4);
    float asum_loc[4] = {0.f, 0.f, 0.f, 0.f};
#pragma unroll
    for (int i = 0; i < 8; i++) {
        float c0 = acc[i][0] + bfr[0];
        float c1 = acc[i][1] + bfr[1];
        float c2 = acc[i][2] + bfr[2];
        float c3 = acc[i][3] + bfr[3];
        float m = fmaxf(fmaxf(c0, c1), fmaxf(c2, c3));
#pragma unroll
        for (int o = 1; o < 16; o <<= 1)
            m = fmaxf(m, __shfl_xor_sync(0xffffffffu, m, o));
        float e0 = __expf(c0 - m), e1 = __expf(c1 - m);
        float e2 = __expf(c2 - m), e3 = __expf(c3 - m);
        float s = e0 + e1 + e2 + e3;
#pragma unroll
        for (int o = 1; o < 16; o <<= 1)
            s += __shfl_xor_sync(0xffffffffu, s, o);
        float inv = 1.0f / s;
        e0 *= inv; e1 *= inv; e2 *= inv; e3 *= inv;
        int row = row0 + ty * 8 + i;
        *(float4*)(g_a + (size_t)row * K_ + tx * 4) = make_float4(e0, e1, e2, e3);
        asum_loc[0] += e0; asum_loc[1] += e1; asum_loc[2] += e2; asum_loc[3] += e3;
    }
    // block-level a_sum reduction, one atomic per (block, k)
#pragma unroll
    for (int j = 0; j < 4; j++) red[ty][tx * 4 + j] = asum_loc[j];
    __syncthreads();
    if (tid < 64) {
        float s = 0.f;
#pragma unroll
        for (int t2 = 0; t2 < 16; t2++) s += red[t2][tid];
        atomicAdd(&g_asum[n * K_ + tid], s);
    }
}

// ---------------------------------------------------------------------------
// K2: per-batch VLAD GEMM  V[d,k] = sum_hw x[n,hw,d] * a[n,hw,k]
// Grid (4 d-tiles, 64 n). BM=128 (d), BN=64 (k), BK=32 (hw).
// Epilogue: V += a_sum[n,k]*C[d,k]; write to out [N,D,K]; accumulate colsq.
// ---------------------------------------------------------------------------
__launch_bounds__(256, 4)
__global__ void vlad_kernel(const float* __restrict__ x,
                            const float* __restrict__ Cc,
                            float* __restrict__ out) {
    __shared__ float As[32][128];   // [hw_k][d] -- natural load, no transpose
    __shared__ float Bs[32][64];    // [hw_k][k]
    __shared__ float red[16][64];

    const int tid = threadIdx.x;
    const int tx = tid & 15;
    const int ty = tid >> 4;
    const int n = blockIdx.y;
    const int m0 = blockIdx.x * 128;

    const float* xn = x + (size_t)n * HW_ * D_;
    const float* an = g_a + (size_t)n * HW_ * K_;

    float acc[8][4];
#pragma unroll
    for (int i = 0; i < 8; i++)
#pragma unroll
        for (int j = 0; j < 4; j++) acc[i][j] = 0.f;

    for (int kt = 0; kt < HW_; kt += 32) {
        {
            int r = tid >> 5;            // 0..7
            int c = (tid & 31) * 4;      // 0..124
#pragma unroll
            for (int p = 0; p < 4; p++) {
                int rr = r + p * 8;
                *(float4*)&As[rr][c] =
                    *(const float4*)(xn + (size_t)(kt + rr) * D_ + m0 + c);
            }
        }
        {
            int r = tid >> 4;
            int c = (tid & 15) * 4;
#pragma unroll
            for (int p = 0; p < 2; p++) {
                int rr = r + p * 16;
                *(float4*)&Bs[rr][c] = *(const float4*)(an + (size_t)(kt + rr) * K_ + c);
            }
        }
        __syncthreads();
#pragma unroll
        for (int kk = 0; kk < 32; kk++) {
            float af[8], bf[4];
            *(float4*)&af[0] = *(const float4*)&As[kk][ty * 8];
            *(float4*)&af[4] = *(const float4*)&As[kk][ty * 8 + 4];
            *(float4*)&bf[0] = *(const float4*)&Bs[kk][tx * 4];
#pragma unroll
            for (int i = 0; i < 8; i++)
#pragma unroll
                for (int j = 0; j < 4; j++)
                    acc[i][j] = fmaf(af[i], bf[j], acc[i][j]);
        }
        __syncthreads();
    }

    // epilogue: + a_sum*C, write v, accumulate column sum-of-squares
    float asv[4];
    *(float4*)asv = *(const float4*)(g_asum + n * K_ + tx * 4);
    float sq[4] = {0.f, 0.f, 0.f, 0.f};
#pragma unroll
    for (int i = 0; i < 8; i++) {
        int d = m0 + ty * 8 + i;
        float4 cc = *(const float4*)(Cc + (size_t)d * K_ + tx * 4);
        float v0 = fmaf(asv[0], cc.x, acc[i][0]);
        float v1 = fmaf(asv[1], cc.y, acc[i][1]);
        float v2 = fmaf(asv[2], cc.z, acc[i][2]);
        float v3 = fmaf(asv[3], cc.w, acc[i][3]);
        sq[0] = fmaf(v0, v0, sq[0]); sq[1] = fmaf(v1, v1, sq[1]);
        sq[2] = fmaf(v2, v2, sq[2]); sq[3] = fmaf(v3, v3, sq[3]);
        *(float4*)(out + ((size_t)n * D_ + d) * K_ + tx * 4) =
            make_float4(v0, v1, v2, v3);
    }
#pragma unroll
    for (int j = 0; j < 4; j++) red[ty][tx * 4 + j] = sq[j];
    __syncthreads();
    if (tid < 64) {
        float s = 0.f;
#pragma unroll
        for (int t2 = 0; t2 < 16; t2++) s += red[t2][tid];
        atomicAdd(&g_colsq[n * K_ + tid], s);
    }
}

// ---------------------------------------------------------------------------
// K3: two-level L2 normalization, in place on out. One block per n.
// intra: w = v / sqrt(S_k + eps); after intra, col sumsq = S_k/(S_k+eps)
// global: / sqrt( sum_k S_k/(S_k+eps) + eps )
// ---------------------------------------------------------------------------
__global__ void norm_kernel(float* __restrict__ out) {
    __shared__ float sc[64];
    __shared__ float contrib[64];
    __shared__ float ginv;

    const int n = blockIdx.x;
    const int tid = threadIdx.x;

    if (tid < 64) {
        float S = g_colsq[n * K_ + tid];
        sc[tid] = rsqrtf(S + EPSF);
        contrib[tid] = S / (S + EPSF);
    }
    __syncthreads();
    if (tid == 0) {
        float g = 0.f;
#pragma unroll
        for (int k = 0; k < 64; k++) g += contrib[k];
        ginv = rsqrtf(g + EPSF);
    }
    __syncthreads();
    if (tid < 64) sc[tid] *= ginv;
    __syncthreads();

    float* po = out + (size_t)n * D_ * K_;
    for (int e = tid * 4; e < D_ * K_; e += blockDim.x * 4) {
        float4 v = *(float4*)(po + e);
        int k = e & 63;            // e multiple of 4; 64 | row length
        v.x *= sc[k + 0]; v.y *= sc[k + 1];
        v.z *= sc[k + 2]; v.w *= sc[k + 3];
        *(float4*)(po + e) = v;
    }
}

// ---------------------------------------------------------------------------
extern "C" void kernel_launch(void* const* d_in, const int* in_sizes, int n_in,
                              void* d_out, int out_size) {
    const float* x  = (const float*)d_in[0];   // [64,32,32,512]
    const float* W  = (const float*)d_in[1];   // [512,64]
    const float* b  = (const float*)d_in[2];   // [64]
    const float* C  = (const float*)d_in[3];   // [512,64]
    float* out = (float*)d_out;                // [64, 32768]

    zero_kernel<<<16, 256>>>();
    assign_kernel<<<ROWS / 128, 256>>>(x, W, b);
    dim3 g2(D_ / 128, N_B);
    vlad_kernel<<<g2, 256>>>(x, C, out);
    norm_kernel<<<N_B, 256>>>(out);
}

// round 6
// speedup vs baseline: 1.6179x; 1.6179x over previous
#include <cuda_runtime.h>
#include <cuda_bf16.h>
#include <cstdint>

#define N_B 64
#define HW_ 1024
#define D_  512
#define K_  64
#define EPSF 1e-12f
#define PADR 72      // bf16 elems per SMEM row (144B): ldmatrix conflict-free
#define RB   144     // row bytes

// ---------------- device scratch (allocation-free rule) ---------------------
__device__ unsigned short g_WTh[K_ * D_];                 // W^T hi bf16 [k][d]
__device__ unsigned short g_WTl[K_ * D_];                 // W^T lo bf16
__device__ unsigned short g_aTh[(size_t)N_B * K_ * HW_];  // a^T hi [n][k][hw]
__device__ unsigned short g_aTl[(size_t)N_B * K_ * HW_];  // a^T lo
__device__ float g_asum[N_B * K_];
__device__ float g_colsq[N_B * K_];

// ---------------- helpers ----------------------------------------------------
__device__ __forceinline__ uint32_t smem_u32(const void* p) {
    uint32_t a;
    asm("{ .reg .u64 t; cvta.to.shared.u64 t, %1; cvt.u32.u64 %0, t; }"
        : "=r"(a) : "l"(p));
    return a;
}
__device__ __forceinline__ void ldm4(uint32_t* r, uint32_t a) {
    asm volatile("ldmatrix.sync.aligned.m8n8.x4.shared.b16 {%0,%1,%2,%3}, [%4];"
                 : "=r"(r[0]), "=r"(r[1]), "=r"(r[2]), "=r"(r[3]) : "r"(a));
}
__device__ __forceinline__ void mma16816(float* d, const uint32_t* a,
                                         const uint32_t* b) {
    asm volatile(
        "mma.sync.aligned.m16n8k16.row.col.f32.bf16.bf16.f32 "
        "{%0,%1,%2,%3}, {%4,%5,%6,%7}, {%8,%9}, {%0,%1,%2,%3};"
        : "+f"(d[0]), "+f"(d[1]), "+f"(d[2]), "+f"(d[3])
        : "r"(a[0]), "r"(a[1]), "r"(a[2]), "r"(a[3]), "r"(b[0]), "r"(b[1]));
}
// split f32 pair -> bf16x2 hi (truncate) + bf16x2 lo (rn of residual)
__device__ __forceinline__ void split2(float x0, float x1, uint32_t& hp, uint32_t& lp) {
    uint32_t u0 = __float_as_uint(x0), u1 = __float_as_uint(x1);
    hp = __byte_perm(u0, u1, 0x7632);
    float l0 = x0 - __uint_as_float(u0 & 0xFFFF0000u);
    float l1 = x1 - __uint_as_float(u1 & 0xFFFF0000u);
    asm("cvt.rn.bf16x2.f32 %0, %1, %2;" : "=r"(lp) : "f"(l1), "f"(l0));
}
// fast exp on FMA pipe. x <= 0 here.
__device__ __forceinline__ float fexp(float x) {
    x = fmaxf(x, -80.0f);
    float t = x * 1.4426950408889634f;
    float tb = t + 12582912.0f;
    float f = t - (tb - 12582912.0f);
    int ei = __float_as_int(tb) - 0x4B400000;
    float p = 1.5403530e-4f;
    p = fmaf(p, f, 1.3333558e-3f);
    p = fmaf(p, f, 9.6181291e-3f);
    p = fmaf(p, f, 5.5504109e-2f);
    p = fmaf(p, f, 2.4022651e-1f);
    p = fmaf(p, f, 6.9314718e-1f);
    p = fmaf(p, f, 1.0f);
    return p * __int_as_float((ei + 127) << 23);
}

// ---------------- K0 + prep --------------------------------------------------
__global__ void zero_kernel() {
    int t = blockIdx.x * blockDim.x + threadIdx.x;
    if (t < N_B * K_) { g_asum[t] = 0.f; g_colsq[t] = 0.f; }
}
__global__ void prep_kernel(const float* __restrict__ W) {
    int t = blockIdx.x * blockDim.x + threadIdx.x;
    if (t < D_ * K_) {
        int d = t >> 6, k = t & 63;
        float w = W[t];
        uint32_t u = __float_as_uint(w);
        g_WTh[k * D_ + d] = (unsigned short)(u >> 16);
        float lo = w - __uint_as_float(u & 0xFFFF0000u);
        __nv_bfloat16 lb = __float2bfloat16(lo);
        g_WTl[k * D_ + d] = *reinterpret_cast<unsigned short*>(&lb);
    }
}

// ---------------- shared compute core: 128x64 tile, 8 warps of 32x32 ---------
// acc[2][4][4]; A rows at AH/AL (stride RB), B rows (64) at BH/BL.
#define MMA_CHUNK(AHp, ALp, BHp, BLp)                                          \
    do {                                                                       \
        _Pragma("unroll")                                                      \
        for (int ks = 0; ks < 4; ks++) {                                       \
            uint32_t ah[2][4], al[2][4], bh[2][4], bl[2][4];                   \
            _Pragma("unroll")                                                  \
            for (int mt = 0; mt < 2; mt++) {                                   \
                uint32_t ad = (AHp) + (wm * 32 + mt * 16 + (lane & 15)) * RB + \
                              (ks * 16 + (lane >> 4) * 8) * 2;                 \
                ldm4(ah[mt], ad);                                              \
                ldm4(al[mt], ad + ((ALp) - (AHp)));                            \
            }                                                                  \
            _Pragma("unroll")                                                  \
            for (int np = 0; np < 2; np++) {                                   \
                uint32_t bd = (BHp) +                                          \
                    (wn * 32 + np * 16 + (lane & 7) + ((lane >> 4) << 3)) * RB \
                    + (ks * 16 + ((lane >> 3) & 1) * 8) * 2;                   \
                ldm4(bh[np], bd);                                              \
                ldm4(bl[np], bd + ((BLp) - (BHp)));                            \
            }                                                                  \
            _Pragma("unroll")                                                  \
            for (int mt = 0; mt < 2; mt++)                                     \
                _Pragma("unroll")                                              \
                for (int nt = 0; nt < 4; nt++) {                               \
                    const uint32_t* bph = &bh[nt >> 1][(nt & 1) * 2];          \
                    const uint32_t* bpl = &bl[nt >> 1][(nt & 1) * 2];          \
                    mma16816(acc[mt][nt], ah[mt], bph);                        \
                    mma16816(acc[mt][nt], ah[mt], bpl);                        \
                    mma16816(acc[mt][nt], al[mt], bph);                        \
                }                                                              \
        }                                                                      \
    } while (0)

// ---------------- GEMM1: assignment + softmax --------------------------------
// SMEM: Ah@0 (18432) Al@18432 Bh@36864 (9216) Bl@46080 bias@55296
#define AH1 0
#define AL1 18432
#define BH1 36864
#define BL1 46080
#define BIAS1 55296
#define SMEM1 55552

__global__ void __launch_bounds__(256, 2)
asg_kernel(const float* __restrict__ x, const float* __restrict__ bc) {
    extern __shared__ char sm[];
    const int tid = threadIdx.x, lane = tid & 31, wid = tid >> 5;
    const int wm = wid & 3, wn = wid >> 2;
    const int row0 = blockIdx.x * 128, n = row0 >> 10;
    const int hw0 = row0 & (HW_ - 1);
    const uint32_t sb = smem_u32(sm);

    if (tid < 64) ((float*)(sm + BIAS1))[tid] = bc[tid];

    float acc[2][4][4];
#pragma unroll
    for (int a = 0; a < 2; a++)
#pragma unroll
        for (int b = 0; b < 4; b++)
#pragma unroll
            for (int c = 0; c < 4; c++) acc[a][b][c] = 0.f;

    for (int ch = 0; ch < 8; ch++) {
        // A: x[128 rows][64 d] f32 -> split -> Ah/Al
        {
            int row = tid >> 1, half = tid & 1;
            const float4* src =
                (const float4*)(x + (size_t)(row0 + row) * D_ + ch * 64 + half * 32);
#pragma unroll
            for (int i = 0; i < 8; i++) {
                float4 v = src[i];
                uint32_t h01, l01, h23, l23;
                split2(v.x, v.y, h01, l01);
                split2(v.z, v.w, h23, l23);
                uint32_t off = row * RB + (half * 32 + i * 4) * 2;
                *(uint2*)(sm + AH1 + off) = make_uint2(h01, h23);
                *(uint2*)(sm + AL1 + off) = make_uint2(l01, l23);
            }
        }
        // B: W^T[64 n][64 d] pre-split
#pragma unroll
        for (int p = 0; p < 2; p++) {
            int idx = tid + p * 256;
            int row = idx >> 3, cg = (idx & 7) * 8;
            uint32_t off = row * RB + cg * 2;
            *(uint4*)(sm + BH1 + off) = *(const uint4*)(g_WTh + row * D_ + ch * 64 + cg);
            *(uint4*)(sm + BL1 + off) = *(const uint4*)(g_WTl + row * D_ + ch * 64 + cg);
        }
        __syncthreads();
        MMA_CHUNK(sb + AH1, sb + AL1, sb + BH1, sb + BL1);
        __syncthreads();
    }

    // scores -> SMEM s[128][66]
    float* s = (float*)sm;
#pragma unroll
    for (int mt = 0; mt < 2; mt++)
#pragma unroll
        for (int nt = 0; nt < 4; nt++) {
            int r = wm * 32 + mt * 16 + (lane >> 2);
            int col = wn * 32 + nt * 8 + 2 * (lane & 3);
            *(float2*)&s[r * 66 + col] = make_float2(acc[mt][nt][0], acc[mt][nt][1]);
            *(float2*)&s[(r + 8) * 66 + col] = make_float2(acc[mt][nt][2], acc[mt][nt][3]);
        }
    __syncthreads();

    if (tid < 128) {
        const float* bias = (const float*)(sm + BIAS1);
        float f[64];
        float m = -1e30f;
#pragma unroll
        for (int k = 0; k < 64; k++) { f[k] = s[tid * 66 + k] + bias[k]; m = fmaxf(m, f[k]); }
        float ssum = 0.f;
#pragma unroll
        for (int k = 0; k < 64; k++) { f[k] = fexp(f[k] - m); ssum += f[k]; }
        float inv = 1.0f / ssum;
        size_t base = (size_t)n * K_ * HW_ + hw0 + tid;   // FIXED: local hw offset
#pragma unroll
        for (int k = 0; k < 64; k++) {
            float a = f[k] * inv;
            uint32_t u = __float_as_uint(a);
            g_aTh[base + (size_t)k * HW_] = (unsigned short)(u >> 16);
            float lo = a - __uint_as_float(u & 0xFFFF0000u);
            __nv_bfloat16 lb = __float2bfloat16(lo);
            g_aTl[base + (size_t)k * HW_] = *reinterpret_cast<unsigned short*>(&lb);
            s[tid * 66 + k] = a;
        }
    }
    __syncthreads();
    if (tid < 64) {
        float acc_s = 0.f;
#pragma unroll 8
        for (int r = 0; r < 128; r++) acc_s += s[r * 66 + tid];
        atomicAdd(&g_asum[n * K_ + tid], acc_s);
    }
}

// ---------------- GEMM2: VLAD ------------------------------------------------
// SMEM: stage f32[64][130]@0 (33280, reused as red[128][65]) Ah@33280 Al@51712
//       Bh@70144 Bl@79360 asum@88576
#define STG2 0
#define AH2 33280
#define AL2 51712
#define BH2 70144
#define BL2 79360
#define AS2 88576
#define SMEM2 88832

__global__ void __launch_bounds__(256, 2)
vlad_kernel(const float* __restrict__ x, const float* __restrict__ Cc,
            float* __restrict__ out) {
    extern __shared__ char sm[];
    const int tid = threadIdx.x, lane = tid & 31, wid = tid >> 5;
    const int wm = wid & 3, wn = wid >> 2;
    const int n = blockIdx.y, m0 = blockIdx.x * 128;
    const uint32_t sb = smem_u32(sm);

    if (tid < 64) ((float*)(sm + AS2))[tid] = g_asum[n * K_ + tid];

    const float* xn = x + (size_t)n * HW_ * D_;
    const unsigned short* ath = g_aTh + (size_t)n * K_ * HW_;
    const unsigned short* atl = g_aTl + (size_t)n * K_ * HW_;
    float* stage = (float*)sm;

    float acc[2][4][4];
#pragma unroll
    for (int a = 0; a < 2; a++)
#pragma unroll
        for (int b = 0; b < 4; b++)
#pragma unroll
            for (int c = 0; c < 4; c++) acc[a][b][c] = 0.f;

    for (int ch = 0; ch < 16; ch++) {
        const int hw0 = ch * 64;
        // stage x chunk [64 hw][128 d] f32 (coalesced)
        {
            int row = tid >> 2;
            const float* src = xn + (size_t)(hw0 + row) * D_ + m0;
#pragma unroll
            for (int i = 0; i < 8; i++) {
                int c4 = ((tid & 3) + i * 4) * 4;
                float4 v = *(const float4*)(src + c4);
                stage[row * 130 + c4 + 0] = v.x;
                stage[row * 130 + c4 + 1] = v.y;
                stage[row * 130 + c4 + 2] = v.z;
                stage[row * 130 + c4 + 3] = v.w;
            }
        }
        // B (a^T pre-split) -> regs
        uint4 rbh[2], rbl[2];
#pragma unroll
        for (int p = 0; p < 2; p++) {
            int idx = tid + p * 256;
            int row = idx >> 3, cg = (idx & 7) * 8;
            rbh[p] = *(const uint4*)(ath + (size_t)row * HW_ + hw0 + cg);
            rbl[p] = *(const uint4*)(atl + (size_t)row * HW_ + hw0 + cg);
        }
        __syncthreads();
        // transpose+split A: [128 d][64 hw]
        {
            int dl = tid & 127, half = tid >> 7;
#pragma unroll
            for (int q = 0; q < 4; q++) {
                float v[8];
#pragma unroll
                for (int j = 0; j < 8; j++)
                    v[j] = stage[(half * 32 + q * 8 + j) * 130 + dl];
                uint32_t hp[4], lp[4];
#pragma unroll
                for (int j = 0; j < 4; j++) split2(v[2 * j], v[2 * j + 1], hp[j], lp[j]);
                uint32_t off = dl * RB + (half * 32 + q * 8) * 2;
                *(uint4*)(sm + AH2 + off) = make_uint4(hp[0], hp[1], hp[2], hp[3]);
                *(uint4*)(sm + AL2 + off) = make_uint4(lp[0], lp[1], lp[2], lp[3]);
            }
        }
        // B STS
#pragma unroll
        for (int p = 0; p < 2; p++) {
            int idx = tid + p * 256;
            int row = idx >> 3, cg = (idx & 7) * 8;
            uint32_t off = row * RB + cg * 2;
            *(uint4*)(sm + BH2 + off) = rbh[p];
            *(uint4*)(sm + BL2 + off) = rbl[p];
        }
        __syncthreads();
        MMA_CHUNK(sb + AH2, sb + AL2, sb + BH2, sb + BL2);
        __syncthreads();
    }

    // epilogue: + a_sum*C, write out, colsq
    const float* asums = (const float*)(sm + AS2);
    float* red = (float*)sm;   // [128][65]
#pragma unroll
    for (int mt = 0; mt < 2; mt++)
#pragma unroll
        for (int nt = 0; nt < 4; nt++) {
            int r0 = wm * 32 + mt * 16 + (lane >> 2);
            int colk = wn * 32 + nt * 8 + 2 * (lane & 3);
#pragma unroll
            for (int h = 0; h < 2; h++) {
                int row = r0 + h * 8, d = m0 + row;
                float2 cc = *(const float2*)(Cc + (size_t)d * K_ + colk);
                float o0 = fmaf(asums[colk], cc.x, acc[mt][nt][h * 2 + 0]);
                float o1 = fmaf(asums[colk + 1], cc.y, acc[mt][nt][h * 2 + 1]);
                *(float2*)(out + ((size_t)n * D_ + d) * K_ + colk) = make_float2(o0, o1);
                red[row * 65 + colk] = o0 * o0;
                red[row * 65 + colk + 1] = o1 * o1;
            }
        }
    __syncthreads();
    if (tid < 64) {
        float s = 0.f;
#pragma unroll 8
        for (int r = 0; r < 128; r++) s += red[r * 65 + tid];
        atomicAdd(&g_colsq[n * K_ + tid], s);
    }
}

// ---------------- norm -------------------------------------------------------
__global__ void norm2_kernel(float* __restrict__ out) {
    __shared__ float S[64];
    __shared__ float sc[64];
    __shared__ float gsh;
    const int n = blockIdx.y, tid = threadIdx.x;
    if (tid < 64) S[tid] = g_colsq[n * K_ + tid];
    __syncthreads();
    if (tid == 0) {
        float s = 0.f;
#pragma unroll
        for (int k = 0; k < 64; k++) s += S[k] / (S[k] + EPSF);
        gsh = rsqrtf(s + EPSF);
    }
    __syncthreads();
    if (tid < 64) sc[tid] = rsqrtf(S[tid] + EPSF) * gsh;
    __syncthreads();
    float* po = out + (size_t)n * D_ * K_ + blockIdx.x * 4096;
#pragma unroll
    for (int i = 0; i < 4; i++) {
        int e = tid * 4 + i * 1024;
        float4 v = *(float4*)(po + e);
        int k = e & 63;
        v.x *= sc[k + 0]; v.y *= sc[k + 1];
        v.z *= sc[k + 2]; v.w *= sc[k + 3];
        *(float4*)(po + e) = v;
    }
}

// ---------------------------------------------------------------------------
extern "C" void kernel_launch(void* const* d_in, const int* in_sizes, int n_in,
                              void* d_out, int out_size) {
    const float* x = (const float*)d_in[0];   // [64,32,32,512]
    const float* W = (const float*)d_in[1];   // [512,64]
    const float* b = (const float*)d_in[2];   // [64]
    const float* C = (const float*)d_in[3];   // [512,64]
    float* out = (float*)d_out;               // [64, 32768]

    cudaFuncSetAttribute(asg_kernel, cudaFuncAttributeMaxDynamicSharedMemorySize, SMEM1);
    cudaFuncSetAttribute(vlad_kernel, cudaFuncAttributeMaxDynamicSharedMemorySize, SMEM2);

    zero_kernel<<<16, 256>>>();
    prep_kernel<<<128, 256>>>(W);
    asg_kernel<<<512, 256, SMEM1>>>(x, b);
    vlad_kernel<<<dim3(4, 64), 256, SMEM2>>>(x, C, out);
    norm2_kernel<<<dim3(8, 64), 256>>>(out);
}